// round 11
// baseline (speedup 1.0000x reference)
#include <cuda_runtime.h>
#include <cuda_bf16.h>
#include <cstdint>
#include <stdint.h>
#include <math.h>

#define BB 2
#define SS 2048
#define HH 1024
#define NH 16
#define HD 64
#define MTOT (BB*SS)   // 4096

// Scratch (static device allocation — allowed)
__device__ float g_q[MTOT*HH];
__device__ float g_k[MTOT*HH];
__device__ float g_v[MTOT*HH];
__device__ float g_ctx[MTOT*HH];
__device__ float g_vsuf[BB*NH*65*HD];

// Pre-split bf16 hi/lo operand buffers
__device__ __nv_bfloat16 g_xh[MTOT*HH], g_xl[MTOT*HH];
__device__ __nv_bfloat16 g_wh[4][HH*HH], g_wl[4][HH*HH];
__device__ __nv_bfloat16 g_ch[MTOT*HH], g_cl[MTOT*HH];

// ===========================================================================
// Helpers (sm_80+ portable: ldmatrix + mma.sync + cp.async)
// ===========================================================================
__device__ __forceinline__ uint32_t smem_to_u32(const void* smem_ptr) {
    uint32_t addr;
    asm("{ .reg .u64 tmp; cvta.to.shared.u64 tmp, %1; cvt.u32.u64 %0, tmp; }"
        : "=r"(addr) : "l"(smem_ptr));
    return addr;
}

#define LDSM4(r, addr) \
    asm volatile("ldmatrix.sync.aligned.m8n8.x4.shared.b16 {%0,%1,%2,%3}, [%4];" \
        : "=r"((r)[0]), "=r"((r)[1]), "=r"((r)[2]), "=r"((r)[3]) : "r"(addr))

#define MMA_BF16(d, a, b) \
    asm volatile("mma.sync.aligned.m16n8k16.row.col.f32.bf16.bf16.f32 " \
        "{%0,%1,%2,%3}, {%4,%5,%6,%7}, {%8,%9}, {%0,%1,%2,%3};" \
        : "+f"((d)[0]), "+f"((d)[1]), "+f"((d)[2]), "+f"((d)[3]) \
        : "r"((a)[0]), "r"((a)[1]), "r"((a)[2]), "r"((a)[3]), \
          "r"((b)[0]), "r"((b)[1]))

#define STS64V(addr, r0, r1) \
    asm volatile("st.shared.v2.b32 [%0], {%1, %2};" :: "r"(addr), "r"(r0), "r"(r1) : "memory")

#define CP16(dst, src) \
    asm volatile("cp.async.cg.shared.global [%0], [%1], 16;" \
        :: "r"(dst), "l"(src) : "memory")
#define CP_COMMIT() asm volatile("cp.async.commit_group;" ::: "memory")
#define CP_WAIT1()  asm volatile("cp.async.wait_group 1;" ::: "memory")

__device__ __forceinline__ uint32_t pack_bf162(__nv_bfloat16 a, __nv_bfloat16 b) {
    __nv_bfloat162 t = __halves2bfloat162(a, b);
    return *reinterpret_cast<uint32_t*>(&t);
}

// split (x,y) into bf16 hi pair + bf16 lo-residual pair
__device__ __forceinline__ void split2(float x, float y, uint32_t& hi, uint32_t& lo) {
    __nv_bfloat16 hx = __float2bfloat16_rn(x);
    __nv_bfloat16 hy = __float2bfloat16_rn(y);
    float rx = x - __bfloat162float(hx);
    float ry = y - __bfloat162float(hy);
    hi = pack_bf162(hx, hy);
    lo = pack_bf162(__float2bfloat16_rn(rx), __float2bfloat16_rn(ry));
}

// ---------------------------------------------------------------------------
// Pre-split: fp32 tensor -> bf16 hi + bf16 lo  (memory-bound, vectorized x4)
// ---------------------------------------------------------------------------
__global__ void __launch_bounds__(256) split_kernel(
    const float* __restrict__ src, __nv_bfloat16* __restrict__ hi,
    __nv_bfloat16* __restrict__ lo, int n4)
{
    int i = blockIdx.x * blockDim.x + threadIdx.x;
    if (i < n4) {
        float4 v = ((const float4*)src)[i];
        uint32_t h0, l0, h1, l1;
        split2(v.x, v.y, h0, l0);
        split2(v.z, v.w, h1, l1);
        ((uint2*)hi)[i] = make_uint2(h0, h1);
        ((uint2*)lo)[i] = make_uint2(l0, l1);
    }
}

// ===========================================================================
// Tensor-core GEMM (pre-split bf16 inputs, cp.async 3-stage pipeline)
// C[m,n] = sum_k A[m,k]*W[n,k] + bias[n]; M=4096, N=1024, K=1024.
// CTA 128x128, BK=32, 256 thr (8 warps @ 64x32).
// D += Ah*Bh + Ah*Bl + Al*Bh (fp32 accum in regs).
// Stage: Ah/Al/Bh/Bl each 128 rows x 40 elems (pad) x 2B = 10240B -> 40960B.
// 3 stages = 122880B dynamic smem.
// ===========================================================================
#define SA 40                    // padded row stride in bf16 elems (80B)
#define AH_OFF 0u
#define AL_OFF 10240u
#define BH_OFF 20480u
#define BL_OFF 30720u
#define STAGE_BYTES 40960u
#define GEMM_SMEM (3*40960)

__global__ void __launch_bounds__(256) gemm_bf16(
    const __nv_bfloat16* __restrict__ Ah, const __nv_bfloat16* __restrict__ Al,
    const __nv_bfloat16* __restrict__ Wh0, const __nv_bfloat16* __restrict__ Wh1,
    const __nv_bfloat16* __restrict__ Wh2,
    const __nv_bfloat16* __restrict__ Wl0, const __nv_bfloat16* __restrict__ Wl1,
    const __nv_bfloat16* __restrict__ Wl2,
    const float* __restrict__ bias0, const float* __restrict__ bias1,
    const float* __restrict__ bias2,
    float* __restrict__ C0, float* __restrict__ C1, float* __restrict__ C2)
{
    const __nv_bfloat16* Wh; const __nv_bfloat16* Wl;
    const float* bias; float* C;
    if (blockIdx.z == 0)      { Wh = Wh0; Wl = Wl0; bias = bias0; C = C0; }
    else if (blockIdx.z == 1) { Wh = Wh1; Wl = Wl1; bias = bias1; C = C1; }
    else                      { Wh = Wh2; Wl = Wl2; bias = bias2; C = C2; }

    extern __shared__ char sm_raw[];
    uint32_t smem_base = smem_to_u32(sm_raw);
    int tid  = threadIdx.x;
    int wid  = tid >> 5;
    int lane = tid & 31;
    int wm = wid >> 2;           // 0..1
    int wn = wid & 3;            // 0..3

    int m0 = blockIdx.y * 128;
    int n0 = blockIdx.x * 128;

    // cp.async mapping: thread t -> row t>>1, elem offset (t&1)*16, 2x16B
    int crow = tid >> 1;
    int cel  = (tid & 1) * 16;
    const __nv_bfloat16* pAh = Ah + (size_t)(m0 + crow) * HH + cel;
    const __nv_bfloat16* pAl = Al + (size_t)(m0 + crow) * HH + cel;
    const __nv_bfloat16* pWh = Wh + (size_t)(n0 + crow) * HH + cel;
    const __nv_bfloat16* pWl = Wl + (size_t)(n0 + crow) * HH + cel;
    uint32_t stsOff = (uint32_t)((crow * SA + cel) * 2);

    uint32_t offA = (uint32_t)(((lane & 15) * SA + (lane >> 4) * 8) * 2);
    uint32_t offB = (uint32_t)((((lane & 7) + ((lane >> 4) << 3)) * SA
                               + ((lane >> 3) & 1) * 8) * 2);

    float acc[4][4][4];
    #pragma unroll
    for (int i = 0; i < 4; ++i)
        #pragma unroll
        for (int j = 0; j < 4; ++j)
            #pragma unroll
            for (int c = 0; c < 4; ++c) acc[i][j][c] = 0.f;

    const int NSTAGE = HH / 32;   // 32

    // prologue: stage slabs 0 and 1
    #pragma unroll
    for (int p = 0; p < 2; ++p) {
        uint32_t stg = smem_base + (uint32_t)p * STAGE_BYTES;
        int kt = p * 32;
        CP16(stg + AH_OFF + stsOff,      pAh + kt);
        CP16(stg + AH_OFF + stsOff + 16, pAh + kt + 8);
        CP16(stg + AL_OFF + stsOff,      pAl + kt);
        CP16(stg + AL_OFF + stsOff + 16, pAl + kt + 8);
        CP16(stg + BH_OFF + stsOff,      pWh + kt);
        CP16(stg + BH_OFF + stsOff + 16, pWh + kt + 8);
        CP16(stg + BL_OFF + stsOff,      pWl + kt);
        CP16(stg + BL_OFF + stsOff + 16, pWl + kt + 8);
        CP_COMMIT();
    }

    for (int s = 0; s < NSTAGE; ++s) {
        CP_WAIT1();
        __syncthreads();

        // issue loads for slab s+2 into buffer (s+2)%3 (always commit a group)
        if (s + 2 < NSTAGE) {
            uint32_t stg = smem_base + (uint32_t)((s + 2) % 3) * STAGE_BYTES;
            int kt = (s + 2) * 32;
            CP16(stg + AH_OFF + stsOff,      pAh + kt);
            CP16(stg + AH_OFF + stsOff + 16, pAh + kt + 8);
            CP16(stg + AL_OFF + stsOff,      pAl + kt);
            CP16(stg + AL_OFF + stsOff + 16, pAl + kt + 8);
            CP16(stg + BH_OFF + stsOff,      pWh + kt);
            CP16(stg + BH_OFF + stsOff + 16, pWh + kt + 8);
            CP16(stg + BL_OFF + stsOff,      pWl + kt);
            CP16(stg + BL_OFF + stsOff + 16, pWl + kt + 8);
        }
        CP_COMMIT();

        uint32_t stg = smem_base + (uint32_t)(s % 3) * STAGE_BYTES;
        uint32_t aBaseH = stg + AH_OFF + offA + (uint32_t)((wm * 64) * SA * 2);
        uint32_t aBaseL = stg + AL_OFF + offA + (uint32_t)((wm * 64) * SA * 2);
        uint32_t bBaseH = stg + BH_OFF + offB + (uint32_t)((wn * 32) * SA * 2);
        uint32_t bBaseL = stg + BL_OFF + offB + (uint32_t)((wn * 32) * SA * 2);

        #pragma unroll
        for (int ks = 0; ks < 2; ++ks) {
            uint32_t kOff = (uint32_t)(ks * 16 * 2);
            uint32_t ah[4][4], al[4][4], bh[4][2], bl[4][2];
            #pragma unroll
            for (int mf = 0; mf < 4; ++mf) {
                uint32_t moff = (uint32_t)(mf * 16 * SA * 2) + kOff;
                LDSM4(ah[mf], aBaseH + moff);
                LDSM4(al[mf], aBaseL + moff);
            }
            #pragma unroll
            for (int nf2 = 0; nf2 < 2; ++nf2) {
                uint32_t noff = (uint32_t)(nf2 * 16 * SA * 2) + kOff;
                uint32_t t4[4];
                LDSM4(t4, bBaseH + noff);
                bh[2*nf2][0] = t4[0]; bh[2*nf2][1] = t4[1];
                bh[2*nf2+1][0] = t4[2]; bh[2*nf2+1][1] = t4[3];
                LDSM4(t4, bBaseL + noff);
                bl[2*nf2][0] = t4[0]; bl[2*nf2][1] = t4[1];
                bl[2*nf2+1][0] = t4[2]; bl[2*nf2+1][1] = t4[3];
            }
            #pragma unroll
            for (int mf = 0; mf < 4; ++mf)
                #pragma unroll
                for (int nf = 0; nf < 4; ++nf) {
                    MMA_BF16(acc[mf][nf], ah[mf], bh[nf]);
                    MMA_BF16(acc[mf][nf], ah[mf], bl[nf]);
                    MMA_BF16(acc[mf][nf], al[mf], bh[nf]);
                }
        }
        __syncthreads();
    }

    // epilogue: acc -> C (+bias)
    int lq = lane >> 2;
    int lr = lane & 3;
    #pragma unroll
    for (int nf = 0; nf < 4; ++nf) {
        int gn = n0 + wn * 32 + nf * 8 + lr * 2;
        float b0 = bias[gn], b1 = bias[gn + 1];
        #pragma unroll
        for (int mf = 0; mf < 4; ++mf) {
            int gm = m0 + wm * 64 + mf * 16 + lq;
            *(float2*)(C + (size_t)gm * HH + gn) =
                make_float2(acc[mf][nf][0] + b0, acc[mf][nf][1] + b1);
            *(float2*)(C + (size_t)(gm + 8) * HH + gn) =
                make_float2(acc[mf][nf][2] + b0, acc[mf][nf][3] + b1);
        }
    }
}

// ---------------------------------------------------------------------------
// Suffix sums of V per (b,h): vsuf[bh][blk][d] = sum_{j >= blk*32} v[b,j,h,d]
// ---------------------------------------------------------------------------
__global__ void __launch_bounds__(256) suffix_kernel(const float* __restrict__ v,
                                                     float* __restrict__ vsuf)
{
    int bh = blockIdx.x;
    int b = bh >> 4, h = bh & 15;
    int d = threadIdx.x & 63;
    int g = threadIdx.x >> 6;

    __shared__ float ps[4][16][64];

    size_t vbase = (size_t)b * SS * HH + (size_t)h * HD + d;

    float acc = 0.f;
    for (int t = 15; t >= 0; --t) {
        int jbase = g * 512 + t * 32;
        #pragma unroll
        for (int jj = 31; jj >= 0; --jj)
            acc += v[vbase + (size_t)(jbase + jj) * HH];
        ps[g][t][d] = acc;
    }
    __syncthreads();

    float offset = 0.f;
    for (int g2 = g + 1; g2 < 4; ++g2) offset += ps[g2][0][d];

    for (int t = 0; t < 16; ++t) {
        int blk = g * 16 + t;
        vsuf[((size_t)bh * 65 + blk) * HD + d] = ps[g][t][d] + offset;
    }
    if (g == 3)
        vsuf[((size_t)bh * 65 + 64) * HD + d] = 0.f;
}

// ===========================================================================
// Tensor-core block-causal attention (unchanged from round 10 — passing)
// ===========================================================================
#define APAD 72
#define SQH 0
#define SQL 18432
#define SKH 36864
#define SKL 46080
#define SVH 55296
#define SVL 64512
#define ATTN_SMEM 73728

__global__ void __launch_bounds__(256) attn_mma(
    const float* __restrict__ gq, const float* __restrict__ gk,
    const float* __restrict__ gv, const float* __restrict__ vsuf,
    float* __restrict__ gctx)
{
    int qt = (int)gridDim.x - 1 - (int)blockIdx.x;  // heavy tiles first
    int h  = blockIdx.y;
    int b  = blockIdx.z;

    extern __shared__ char sm[];
    uint32_t smb = smem_to_u32(sm);

    int tid = threadIdx.x;
    int wid = tid >> 5, lane = tid & 31;
    int wm = wid >> 1;            // 0..3 : rows wm*32
    int wn = wid & 1;             // 0..1 : keys wn*32
    int m0 = qt * 128;
    size_t base = (size_t)b * SS * HH + (size_t)h * HD;

    uint32_t offA = (uint32_t)(((lane & 15) * APAD + (lane >> 4) * 8) * 2);
    uint32_t offB = (uint32_t)((((lane & 7) + ((lane >> 4) << 3)) * APAD
                               + ((lane >> 3) & 1) * 8) * 2);

    // ---- load Q tile (split hi/lo)
    {
        int row = tid >> 1, hc = (tid & 1) * 32;
        const float* Qp = gq + base + (size_t)(m0 + row) * HH + hc;
        #pragma unroll
        for (int f = 0; f < 8; ++f) {
            float4 qv = *(const float4*)(Qp + 4 * f);
            uint32_t h0, l0, h1, l1;
            split2(qv.x, qv.y, h0, l0);
            split2(qv.z, qv.w, h1, l1);
            uint32_t o = (uint32_t)((row * APAD + hc + 4 * f) * 2);
            STS64V(smb + SQH + o, h0, h1);
            STS64V(smb + SQL + o, l0, l1);
        }
    }

    float cacc[2][8][4];
    #pragma unroll
    for (int mi = 0; mi < 2; ++mi)
        #pragma unroll
        for (int nf = 0; nf < 8; ++nf)
            #pragma unroll
            for (int c = 0; c < 4; ++c) cacc[mi][nf][c] = 0.f;
    float dsum[2][2] = {{0.f, 0.f}, {0.f, 0.f}};

    int Lm[2];
    #pragma unroll
    for (int mi = 0; mi < 2; ++mi)
        Lm[mi] = (((m0 + wm * 32 + mi * 16) >> 5) + 1) << 5;

    int nkt = 2 * qt + 2;
    for (int kt = 0; kt < nkt; ++kt) {
        int j0 = kt * 64;

        // ---- K tile [key][d] split
        {
            int row = tid >> 2, qc = (tid & 3) * 16;
            const float* Kp = gk + base + (size_t)(j0 + row) * HH + qc;
            #pragma unroll
            for (int f = 0; f < 4; ++f) {
                float4 kv = *(const float4*)(Kp + 4 * f);
                uint32_t h0, l0, h1, l1;
                split2(kv.x, kv.y, h0, l0);
                split2(kv.z, kv.w, h1, l1);
                uint32_t o = (uint32_t)((row * APAD + qc + 4 * f) * 2);
                STS64V(smb + SKH + o, h0, h1);
                STS64V(smb + SKL + o, l0, l1);
            }
        }
        // ---- V tile transposed [d][key] split (coalesced LDG: lane = d)
        {
            int d = tid & 63, jg = tid >> 6;
            const float* Vp = gv + base + d + (size_t)(j0 + jg * 16) * HH;
            __nv_bfloat16* vh = (__nv_bfloat16*)(sm + SVH);
            __nv_bfloat16* vl = (__nv_bfloat16*)(sm + SVL);
            #pragma unroll
            for (int jj = 0; jj < 16; ++jj) {
                float val = Vp[(size_t)jj * HH];
                __nv_bfloat16 hv = __float2bfloat16_rn(val);
                float lv = val - __bfloat162float(hv);
                int j = jg * 16 + jj;
                vh[d * APAD + j] = hv;
                vl[d * APAD + j] = __float2bfloat16_rn(lv);
            }
        }
        __syncthreads();

        // ---- S = Q @ K^T  (3-pass split), warp tile 32 rows x 32 keys
        float sacc[2][4][4];
        #pragma unroll
        for (int mi = 0; mi < 2; ++mi)
            #pragma unroll
            for (int ni = 0; ni < 4; ++ni)
                #pragma unroll
                for (int c = 0; c < 4; ++c) sacc[mi][ni][c] = 0.f;

        #pragma unroll
        for (int kk = 0; kk < 4; ++kk) {
            uint32_t kof = (uint32_t)(kk * 16 * 2);
            uint32_t aqh[2][4], aql[2][4], bkh[4][2], bkl[4][2];
            #pragma unroll
            for (int mi = 0; mi < 2; ++mi) {
                uint32_t mo = (uint32_t)((wm * 32 + mi * 16) * APAD * 2) + kof;
                LDSM4(aqh[mi], smb + SQH + mo + offA);
                LDSM4(aql[mi], smb + SQL + mo + offA);
            }
            #pragma unroll
            for (int nf2 = 0; nf2 < 2; ++nf2) {
                uint32_t no = (uint32_t)((wn * 32 + nf2 * 16) * APAD * 2) + kof;
                uint32_t t4[4];
                LDSM4(t4, smb + SKH + no + offB);
                bkh[2*nf2][0] = t4[0]; bkh[2*nf2][1] = t4[1];
                bkh[2*nf2+1][0] = t4[2]; bkh[2*nf2+1][1] = t4[3];
                LDSM4(t4, smb + SKL + no + offB);
                bkl[2*nf2][0] = t4[0]; bkl[2*nf2][1] = t4[1];
                bkl[2*nf2+1][0] = t4[2]; bkl[2*nf2+1][1] = t4[3];
            }
            #pragma unroll
            for (int mi = 0; mi < 2; ++mi)
                #pragma unroll
                for (int ni = 0; ni < 4; ++ni) {
                    MMA_BF16(sacc[mi][ni], aqh[mi], bkh[ni]);
                    MMA_BF16(sacc[mi][ni], aqh[mi], bkl[ni]);
                    MMA_BF16(sacc[mi][ni], aql[mi], bkh[ni]);
                }
        }

        // ---- mask + exp + split P, repack C-frag -> A-frag (no shuffles)
        uint32_t aPh[2][2][4], aPl[2][2][4];
        #pragma unroll
        for (int mi = 0; mi < 2; ++mi) {
            int L = Lm[mi];
            #pragma unroll
            for (int ni = 0; ni < 4; ++ni) {
                int g0 = j0 + wn * 32 + ni * 8 + 2 * (lane & 3);
                bool a0 = (g0 < L), a1 = (g0 + 1 < L);
                float p0 = a0 ? __expf(sacc[mi][ni][0] * 0.125f) : 0.f;
                float p1 = a1 ? __expf(sacc[mi][ni][1] * 0.125f) : 0.f;
                float p2 = a0 ? __expf(sacc[mi][ni][2] * 0.125f) : 0.f;
                float p3 = a1 ? __expf(sacc[mi][ni][3] * 0.125f) : 0.f;
                dsum[mi][0] += p0 + p1;
                dsum[mi][1] += p2 + p3;
                __nv_bfloat16 h0 = __float2bfloat16_rn(p0);
                __nv_bfloat16 h1 = __float2bfloat16_rn(p1);
                __nv_bfloat16 h2 = __float2bfloat16_rn(p2);
                __nv_bfloat16 h3 = __float2bfloat16_rn(p3);
                float q0 = p0 - __bfloat162float(h0);
                float q1 = p1 - __bfloat162float(h1);
                float q2 = p2 - __bfloat162float(h2);
                float q3 = p3 - __bfloat162float(h3);
                int kp = ni >> 1, hf = ni & 1;
                aPh[mi][kp][2*hf + 0] = pack_bf162(h0, h1);
                aPh[mi][kp][2*hf + 1] = pack_bf162(h2, h3);
                aPl[mi][kp][2*hf + 0] = pack_bf162(__float2bfloat16_rn(q0),
                                                   __float2bfloat16_rn(q1));
                aPl[mi][kp][2*hf + 1] = pack_bf162(__float2bfloat16_rn(q2),
                                                   __float2bfloat16_rn(q3));
            }
        }

        // ---- ctx += P @ V  (3-pass split), warp keys slice = wn*32 .. +31
        #pragma unroll
        for (int kk2 = 0; kk2 < 2; ++kk2) {
            uint32_t bvh[8][2], bvl[8][2];
            #pragma unroll
            for (int nf2 = 0; nf2 < 4; ++nf2) {
                uint32_t no = (uint32_t)((nf2 * 16) * APAD * 2
                                        + (wn * 32 + kk2 * 16) * 2);
                uint32_t t4[4];
                LDSM4(t4, smb + SVH + no + offB);
                bvh[2*nf2][0] = t4[0]; bvh[2*nf2][1] = t4[1];
                bvh[2*nf2+1][0] = t4[2]; bvh[2*nf2+1][1] = t4[3];
                LDSM4(t4, smb + SVL + no + offB);
                bvl[2*nf2][0] = t4[0]; bvl[2*nf2][1] = t4[1];
                bvl[2*nf2+1][0] = t4[2]; bvl[2*nf2+1][1] = t4[3];
            }
            #pragma unroll
            for (int mi = 0; mi < 2; ++mi)
                #pragma unroll
                for (int nf = 0; nf < 8; ++nf) {
                    MMA_BF16(cacc[mi][nf], aPh[mi][kk2], bvh[nf]);
                    MMA_BF16(cacc[mi][nf], aPh[mi][kk2], bvl[nf]);
                    MMA_BF16(cacc[mi][nf], aPl[mi][kk2], bvh[nf]);
                }
        }
        __syncthreads();
    }

    // ---- quad-reduce denominators (rows spread over lane%4)
    #pragma unroll
    for (int mi = 0; mi < 2; ++mi)
        #pragma unroll
        for (int hf = 0; hf < 2; ++hf) {
            float v = dsum[mi][hf];
            v += __shfl_xor_sync(0xffffffffu, v, 1);
            v += __shfl_xor_sync(0xffffffffu, v, 2);
            dsum[mi][hf] = v;
        }

    // ---- cross-warp (wn) reduction via smem aliased over Q region
    float* ctxbuf = (float*)sm;                 // [128][66]
    float* dnb    = (float*)sm + 128 * 66;      // [128]

    if (wn == 0) {
        int r0 = wm * 32 + (lane >> 2);
        #pragma unroll
        for (int mi = 0; mi < 2; ++mi) {
            if ((lane & 3) == 0) {
                dnb[r0 + mi * 16]     = dsum[mi][0];
                dnb[r0 + mi * 16 + 8] = dsum[mi][1];
            }
            #pragma unroll
            for (int nf = 0; nf < 8; ++nf) {
                int col = nf * 8 + 2 * (lane & 3);
                *(float2*)&ctxbuf[(r0 + mi * 16) * 66 + col] =
                    make_float2(cacc[mi][nf][0], cacc[mi][nf][1]);
                *(float2*)&ctxbuf[(r0 + mi * 16 + 8) * 66 + col] =
                    make_float2(cacc[mi][nf][2], cacc[mi][nf][3]);
            }
        }
    }
    __syncthreads();

    if (wn == 1) {
        int bh = b * NH + h;
        int r0 = wm * 32 + (lane >> 2);
        #pragma unroll
        for (int mi = 0; mi < 2; ++mi) {
            int rA = r0 + mi * 16, rB = rA + 8;
            float zc = (float)(SS - Lm[mi]);
            float di0 = 1.f / (dsum[mi][0] + dnb[rA] + zc);
            float di1 = 1.f / (dsum[mi][1] + dnb[rB] + zc);
            int blkp1 = Lm[mi] >> 5;
            const float* suf = vsuf + ((size_t)bh * 65 + blkp1) * HD;
            #pragma unroll
            for (int nf = 0; nf < 8; ++nf) {
                int col = nf * 8 + 2 * (lane & 3);
                float2 o0 = *(float2*)&ctxbuf[rA * 66 + col];
                float2 o1 = *(float2*)&ctxbuf[rB * 66 + col];
                float2 sv = *(const float2*)(suf + col);
                float2 w0 = make_float2((cacc[mi][nf][0] + o0.x + sv.x) * di0,
                                        (cacc[mi][nf][1] + o0.y + sv.y) * di0);
                float2 w1 = make_float2((cacc[mi][nf][2] + o1.x + sv.x) * di1,
                                        (cacc[mi][nf][3] + o1.y + sv.y) * di1);
                *(float2*)(gctx + base + (size_t)(m0 + rA) * HH + col) = w0;
                *(float2*)(gctx + base + (size_t)(m0 + rB) * HH + col) = w1;
            }
        }
    }
}

// ---------------------------------------------------------------------------
extern "C" void kernel_launch(void* const* d_in, const int* in_sizes, int n_in,
                              void* d_out, int out_size)
{
    const float* x  = (const float*)d_in[0];
    const float* Wq = (const float*)d_in[1];
    const float* bq = (const float*)d_in[2];
    const float* Wk = (const float*)d_in[3];
    const float* bk = (const float*)d_in[4];
    const float* Wv = (const float*)d_in[5];
    const float* bv = (const float*)d_in[6];
    const float* Wo = (const float*)d_in[7];
    const float* bo = (const float*)d_in[8];
    float* out = (float*)d_out;

    float *q, *k, *v, *ctx, *vsuf;
    cudaGetSymbolAddress((void**)&q,    g_q);
    cudaGetSymbolAddress((void**)&k,    g_k);
    cudaGetSymbolAddress((void**)&v,    g_v);
    cudaGetSymbolAddress((void**)&ctx,  g_ctx);
    cudaGetSymbolAddress((void**)&vsuf, g_vsuf);

    __nv_bfloat16 *xh, *xl, *wh, *wl, *ch, *cl;
    cudaGetSymbolAddress((void**)&xh, g_xh);
    cudaGetSymbolAddress((void**)&xl, g_xl);
    cudaGetSymbolAddress((void**)&wh, g_wh);
    cudaGetSymbolAddress((void**)&wl, g_wl);
    cudaGetSymbolAddress((void**)&ch, g_ch);
    cudaGetSymbolAddress((void**)&cl, g_cl);

    cudaFuncSetAttribute(gemm_bf16, cudaFuncAttributeMaxDynamicSharedMemorySize,
                         GEMM_SMEM);
    cudaFuncSetAttribute(attn_mma, cudaFuncAttributeMaxDynamicSharedMemorySize,
                         ATTN_SMEM);

    const int WN = HH * HH;            // 1M elems per weight
    // 0) pre-split operands to bf16 hi/lo
    split_kernel<<<MTOT*HH/4/256, 256>>>(x,  xh, xl, MTOT*HH/4);
    split_kernel<<<WN/4/256, 256>>>(Wq, wh + 0*WN, wl + 0*WN, WN/4);
    split_kernel<<<WN/4/256, 256>>>(Wk, wh + 1*WN, wl + 1*WN, WN/4);
    split_kernel<<<WN/4/256, 256>>>(Wv, wh + 2*WN, wl + 2*WN, WN/4);
    split_kernel<<<WN/4/256, 256>>>(Wo, wh + 3*WN, wl + 3*WN, WN/4);

    // 1) fused QKV projections (cp.async pipelined bf16 GEMM)
    gemm_bf16<<<dim3(8, 32, 3), 256, GEMM_SMEM>>>(
        xh, xl,
        wh + 0*WN, wh + 1*WN, wh + 2*WN,
        wl + 0*WN, wl + 1*WN, wl + 2*WN,
        bq, bk, bv, q, k, v);

    // 2) suffix sums of V
    suffix_kernel<<<32, 256>>>(v, vsuf);

    // 3) block-causal attention with zero-score correction (tensor cores)
    attn_mma<<<dim3(16, NH, BB), 256, ATTN_SMEM>>>(q, k, v, vsuf, ctx);

    // 4) split ctx, then output projection -> d_out
    split_kernel<<<MTOT*HH/4/256, 256>>>(ctx, ch, cl, MTOT*HH/4);
    gemm_bf16<<<dim3(8, 32, 1), 256, GEMM_SMEM>>>(
        ch, cl,
        wh + 3*WN, wh + 3*WN, wh + 3*WN,
        wl + 3*WN, wl + 3*WN, wl + 3*WN,
        bo, bo, bo, out, out, out);
}

// round 12
// speedup vs baseline: 1.0811x; 1.0811x over previous
#include <cuda_runtime.h>
#include <cuda_bf16.h>
#include <cstdint>
#include <stdint.h>
#include <math.h>

#define BB 2
#define SS 2048
#define HH 1024
#define NH 16
#define HD 64
#define MTOT (BB*SS)   // 4096

// Scratch (static device allocation — allowed)
__device__ float g_q[MTOT*HH];
__device__ float g_k[MTOT*HH];
__device__ float g_v[MTOT*HH];
__device__ float g_ctx[MTOT*HH];
__device__ float g_vsuf[BB*NH*65*HD];

// ===========================================================================
// Helpers (sm_80+ portable: ldmatrix + mma.sync)
// ===========================================================================
__device__ __forceinline__ uint32_t smem_to_u32(const void* smem_ptr) {
    uint32_t addr;
    asm("{ .reg .u64 tmp; cvta.to.shared.u64 tmp, %1; cvt.u32.u64 %0, tmp; }"
        : "=r"(addr) : "l"(smem_ptr));
    return addr;
}

#define LDSM4(r, addr) \
    asm volatile("ldmatrix.sync.aligned.m8n8.x4.shared.b16 {%0,%1,%2,%3}, [%4];" \
        : "=r"((r)[0]), "=r"((r)[1]), "=r"((r)[2]), "=r"((r)[3]) : "r"(addr))

#define MMA_BF16(d, a, b) \
    asm volatile("mma.sync.aligned.m16n8k16.row.col.f32.bf16.bf16.f32 " \
        "{%0,%1,%2,%3}, {%4,%5,%6,%7}, {%8,%9}, {%0,%1,%2,%3};" \
        : "+f"((d)[0]), "+f"((d)[1]), "+f"((d)[2]), "+f"((d)[3]) \
        : "r"((a)[0]), "r"((a)[1]), "r"((a)[2]), "r"((a)[3]), \
          "r"((b)[0]), "r"((b)[1]))

#define STS64V(addr, r0, r1) \
    asm volatile("st.shared.v2.b32 [%0], {%1, %2};" :: "r"(addr), "r"(r0), "r"(r1) : "memory")

__device__ __forceinline__ uint32_t pack_bf162(__nv_bfloat16 a, __nv_bfloat16 b) {
    __nv_bfloat162 t = __halves2bfloat162(a, b);
    return *reinterpret_cast<uint32_t*>(&t);
}

// split (x,y) into bf16 hi pair + bf16 lo-residual pair
__device__ __forceinline__ void split2(float x, float y, uint32_t& hi, uint32_t& lo) {
    __nv_bfloat16 hx = __float2bfloat16_rn(x);
    __nv_bfloat16 hy = __float2bfloat16_rn(y);
    float rx = x - __bfloat162float(hx);
    float ry = y - __bfloat162float(hy);
    hi = pack_bf162(hx, hy);
    lo = pack_bf162(__float2bfloat16_rn(rx), __float2bfloat16_rn(ry));
}

// ===========================================================================
// Tensor-core GEMM via mma.sync: C[m,n] = sum_k A[m,k]*W[n,k] + bias[n]
// M=4096, N=1024, K=1024. CTA 128x128, BK=32, 512 thr (16 warps @ 32x32).
// bf16 two-term split: D += Ah*Bh + Ah*Bl + Al*Bh (fp32 accum in regs).
// SMEM: per stage Ah/Al/Bh/Bl each 128 rows x 40 elems (pad) x 2B = 10240B.
// Stage = 40960B, double buffered = 81920B dynamic smem.
// ===========================================================================
#define SA 40                    // padded row stride in bf16 elems (80B)
#define AH_OFF 0u
#define AL_OFF 10240u
#define BH_OFF 20480u
#define BL_OFF 30720u
#define STAGE_BYTES 40960u
#define GEMM_SMEM (2*40960)

__global__ void __launch_bounds__(512) gemm_tc(
    const float* __restrict__ A,
    const float* __restrict__ W0, const float* __restrict__ W1, const float* __restrict__ W2,
    const float* __restrict__ bias0, const float* __restrict__ bias1, const float* __restrict__ bias2,
    float* __restrict__ C0, float* __restrict__ C1, float* __restrict__ C2)
{
    const float* W; const float* bias; float* C;
    if (blockIdx.z == 0)      { W = W0; bias = bias0; C = C0; }
    else if (blockIdx.z == 1) { W = W1; bias = bias1; C = C1; }
    else                      { W = W2; bias = bias2; C = C2; }

    extern __shared__ char sm_raw[];
    uint32_t smem_base = smem_to_u32(sm_raw);
    int tid  = threadIdx.x;
    int wid  = tid >> 5;
    int lane = tid & 31;
    int wm = wid >> 2;           // 0..3 (32 rows each)
    int wn = wid & 3;            // 0..3 (32 cols each)

    int m0 = blockIdx.y * 128;
    int n0 = blockIdx.x * 128;

    // gmem load mapping: thread t -> row t>>2, col (t&3)*8, 2 float4 per matrix
    int row = tid >> 2;
    int cb  = (tid & 3) * 8;
    const float* Ap = A + (size_t)(m0 + row) * HH + cb;
    const float* Wp = W + (size_t)(n0 + row) * HH + cb;
    uint32_t stsOff[2];
    #pragma unroll
    for (int f = 0; f < 2; ++f)
        stsOff[f] = (uint32_t)((row * SA + cb + 4 * f) * 2);

    uint32_t offA = (uint32_t)(((lane & 15) * SA + (lane >> 4) * 8) * 2);
    uint32_t offB = (uint32_t)((((lane & 7) + ((lane >> 4) << 3)) * SA
                               + ((lane >> 3) & 1) * 8) * 2);

    float acc[2][4][4];
    #pragma unroll
    for (int i = 0; i < 2; ++i)
        #pragma unroll
        for (int j = 0; j < 4; ++j)
            #pragma unroll
            for (int c = 0; c < 4; ++c) acc[i][j][c] = 0.f;

    // preload stage 0
    {
        uint32_t stg = smem_base;
        #pragma unroll
        for (int f = 0; f < 2; ++f) {
            float4 av = *(const float4*)(Ap + 4 * f);
            uint32_t h0, l0, h1, l1;
            split2(av.x, av.y, h0, l0);
            split2(av.z, av.w, h1, l1);
            STS64V(stg + AH_OFF + stsOff[f], h0, h1);
            STS64V(stg + AL_OFF + stsOff[f], l0, l1);
            float4 wv = *(const float4*)(Wp + 4 * f);
            split2(wv.x, wv.y, h0, l0);
            split2(wv.z, wv.w, h1, l1);
            STS64V(stg + BH_OFF + stsOff[f], h0, h1);
            STS64V(stg + BL_OFF + stsOff[f], l0, l1);
        }
    }
    __syncthreads();

    const int NSTAGE = HH / 32;   // 32
    float4 pa[2], pw[2];

    for (int s = 0; s < NSTAGE; ++s) {
        if (s + 1 < NSTAGE) {
            int kt = (s + 1) * 32;
            #pragma unroll
            for (int f = 0; f < 2; ++f) {
                pa[f] = *(const float4*)(Ap + kt + 4 * f);
                pw[f] = *(const float4*)(Wp + kt + 4 * f);
            }
        }

        uint32_t stg = smem_base + (uint32_t)(s & 1) * STAGE_BYTES;
        uint32_t aBaseH = stg + AH_OFF + offA + (uint32_t)((wm * 32) * SA * 2);
        uint32_t aBaseL = stg + AL_OFF + offA + (uint32_t)((wm * 32) * SA * 2);
        uint32_t bBaseH = stg + BH_OFF + offB + (uint32_t)((wn * 32) * SA * 2);
        uint32_t bBaseL = stg + BL_OFF + offB + (uint32_t)((wn * 32) * SA * 2);

        #pragma unroll
        for (int ks = 0; ks < 2; ++ks) {
            uint32_t kOff = (uint32_t)(ks * 16 * 2);
            uint32_t ah[2][4], al[2][4], bh[4][2], bl[4][2];
            #pragma unroll
            for (int mf = 0; mf < 2; ++mf) {
                uint32_t moff = (uint32_t)(mf * 16 * SA * 2) + kOff;
                LDSM4(ah[mf], aBaseH + moff);
                LDSM4(al[mf], aBaseL + moff);
            }
            #pragma unroll
            for (int nf2 = 0; nf2 < 2; ++nf2) {
                uint32_t noff = (uint32_t)(nf2 * 16 * SA * 2) + kOff;
                uint32_t t4[4];
                LDSM4(t4, bBaseH + noff);
                bh[2*nf2][0] = t4[0]; bh[2*nf2][1] = t4[1];
                bh[2*nf2+1][0] = t4[2]; bh[2*nf2+1][1] = t4[3];
                LDSM4(t4, bBaseL + noff);
                bl[2*nf2][0] = t4[0]; bl[2*nf2][1] = t4[1];
                bl[2*nf2+1][0] = t4[2]; bl[2*nf2+1][1] = t4[3];
            }
            #pragma unroll
            for (int mf = 0; mf < 2; ++mf)
                #pragma unroll
                for (int nf = 0; nf < 4; ++nf) {
                    MMA_BF16(acc[mf][nf], ah[mf], bh[nf]);
                    MMA_BF16(acc[mf][nf], ah[mf], bl[nf]);
                    MMA_BF16(acc[mf][nf], al[mf], bh[nf]);
                }
        }

        if (s + 1 < NSTAGE) {
            uint32_t nstg = smem_base + (uint32_t)((s + 1) & 1) * STAGE_BYTES;
            #pragma unroll
            for (int f = 0; f < 2; ++f) {
                uint32_t h0, l0, h1, l1;
                split2(pa[f].x, pa[f].y, h0, l0);
                split2(pa[f].z, pa[f].w, h1, l1);
                STS64V(nstg + AH_OFF + stsOff[f], h0, h1);
                STS64V(nstg + AL_OFF + stsOff[f], l0, l1);
                split2(pw[f].x, pw[f].y, h0, l0);
                split2(pw[f].z, pw[f].w, h1, l1);
                STS64V(nstg + BH_OFF + stsOff[f], h0, h1);
                STS64V(nstg + BL_OFF + stsOff[f], l0, l1);
            }
        }
        __syncthreads();
    }

    // epilogue: acc -> C (+bias)
    int lq = lane >> 2;
    int lr = lane & 3;
    #pragma unroll
    for (int nf = 0; nf < 4; ++nf) {
        int gn = n0 + wn * 32 + nf * 8 + lr * 2;
        float b0 = bias[gn], b1 = bias[gn + 1];
        #pragma unroll
        for (int mf = 0; mf < 2; ++mf) {
            int gm = m0 + wm * 32 + mf * 16 + lq;
            *(float2*)(C + (size_t)gm * HH + gn) =
                make_float2(acc[mf][nf][0] + b0, acc[mf][nf][1] + b1);
            *(float2*)(C + (size_t)(gm + 8) * HH + gn) =
                make_float2(acc[mf][nf][2] + b0, acc[mf][nf][3] + b1);
        }
    }
}

// ---------------------------------------------------------------------------
// Suffix sums of V per (b,h): vsuf[bh][blk][d] = sum_{j >= blk*32} v[b,j,h,d]
// ---------------------------------------------------------------------------
__global__ void __launch_bounds__(256) suffix_kernel(const float* __restrict__ v,
                                                     float* __restrict__ vsuf)
{
    int bh = blockIdx.x;
    int b = bh >> 4, h = bh & 15;
    int d = threadIdx.x & 63;
    int g = threadIdx.x >> 6;

    __shared__ float ps[4][16][64];

    size_t vbase = (size_t)b * SS * HH + (size_t)h * HD + d;

    float acc = 0.f;
    for (int t = 15; t >= 0; --t) {
        int jbase = g * 512 + t * 32;
        #pragma unroll
        for (int jj = 31; jj >= 0; --jj)
            acc += v[vbase + (size_t)(jbase + jj) * HH];
        ps[g][t][d] = acc;
    }
    __syncthreads();

    float offset = 0.f;
    for (int g2 = g + 1; g2 < 4; ++g2) offset += ps[g2][0][d];

    for (int t = 0; t < 16; ++t) {
        int blk = g * 16 + t;
        vsuf[((size_t)bh * 65 + blk) * HD + d] = ps[g][t][d] + offset;
    }
    if (g == 3)
        vsuf[((size_t)bh * 65 + 64) * HD + d] = 0.f;
}

// ===========================================================================
// Tensor-core block-causal attention (unchanged from round 10 — passing)
// ===========================================================================
#define APAD 72
#define SQH 0
#define SQL 18432
#define SKH 36864
#define SKL 46080
#define SVH 55296
#define SVL 64512
#define ATTN_SMEM 73728

__global__ void __launch_bounds__(256) attn_mma(
    const float* __restrict__ gq, const float* __restrict__ gk,
    const float* __restrict__ gv, const float* __restrict__ vsuf,
    float* __restrict__ gctx)
{
    int qt = (int)gridDim.x - 1 - (int)blockIdx.x;  // heavy tiles first
    int h  = blockIdx.y;
    int b  = blockIdx.z;

    extern __shared__ char sm[];
    uint32_t smb = smem_to_u32(sm);

    int tid = threadIdx.x;
    int wid = tid >> 5, lane = tid & 31;
    int wm = wid >> 1;            // 0..3 : rows wm*32
    int wn = wid & 1;             // 0..1 : keys wn*32
    int m0 = qt * 128;
    size_t base = (size_t)b * SS * HH + (size_t)h * HD;

    uint32_t offA = (uint32_t)(((lane & 15) * APAD + (lane >> 4) * 8) * 2);
    uint32_t offB = (uint32_t)((((lane & 7) + ((lane >> 4) << 3)) * APAD
                               + ((lane >> 3) & 1) * 8) * 2);

    // ---- load Q tile (split hi/lo)
    {
        int row = tid >> 1, hc = (tid & 1) * 32;
        const float* Qp = gq + base + (size_t)(m0 + row) * HH + hc;
        #pragma unroll
        for (int f = 0; f < 8; ++f) {
            float4 qv = *(const float4*)(Qp + 4 * f);
            uint32_t h0, l0, h1, l1;
            split2(qv.x, qv.y, h0, l0);
            split2(qv.z, qv.w, h1, l1);
            uint32_t o = (uint32_t)((row * APAD + hc + 4 * f) * 2);
            STS64V(smb + SQH + o, h0, h1);
            STS64V(smb + SQL + o, l0, l1);
        }
    }

    float cacc[2][8][4];
    #pragma unroll
    for (int mi = 0; mi < 2; ++mi)
        #pragma unroll
        for (int nf = 0; nf < 8; ++nf)
            #pragma unroll
            for (int c = 0; c < 4; ++c) cacc[mi][nf][c] = 0.f;
    float dsum[2][2] = {{0.f, 0.f}, {0.f, 0.f}};

    int Lm[2];
    #pragma unroll
    for (int mi = 0; mi < 2; ++mi)
        Lm[mi] = (((m0 + wm * 32 + mi * 16) >> 5) + 1) << 5;

    int nkt = 2 * qt + 2;
    for (int kt = 0; kt < nkt; ++kt) {
        int j0 = kt * 64;

        // ---- K tile [key][d] split
        {
            int row = tid >> 2, qc = (tid & 3) * 16;
            const float* Kp = gk + base + (size_t)(j0 + row) * HH + qc;
            #pragma unroll
            for (int f = 0; f < 4; ++f) {
                float4 kv = *(const float4*)(Kp + 4 * f);
                uint32_t h0, l0, h1, l1;
                split2(kv.x, kv.y, h0, l0);
                split2(kv.z, kv.w, h1, l1);
                uint32_t o = (uint32_t)((row * APAD + qc + 4 * f) * 2);
                STS64V(smb + SKH + o, h0, h1);
                STS64V(smb + SKL + o, l0, l1);
            }
        }
        // ---- V tile transposed [d][key] split (coalesced LDG: lane = d)
        {
            int d = tid & 63, jg = tid >> 6;
            const float* Vp = gv + base + d + (size_t)(j0 + jg * 16) * HH;
            __nv_bfloat16* vh = (__nv_bfloat16*)(sm + SVH);
            __nv_bfloat16* vl = (__nv_bfloat16*)(sm + SVL);
            #pragma unroll
            for (int jj = 0; jj < 16; ++jj) {
                float val = Vp[(size_t)jj * HH];
                __nv_bfloat16 hv = __float2bfloat16_rn(val);
                float lv = val - __bfloat162float(hv);
                int j = jg * 16 + jj;
                vh[d * APAD + j] = hv;
                vl[d * APAD + j] = __float2bfloat16_rn(lv);
            }
        }
        __syncthreads();

        // ---- S = Q @ K^T  (3-pass split), warp tile 32 rows x 32 keys
        float sacc[2][4][4];
        #pragma unroll
        for (int mi = 0; mi < 2; ++mi)
            #pragma unroll
            for (int ni = 0; ni < 4; ++ni)
                #pragma unroll
                for (int c = 0; c < 4; ++c) sacc[mi][ni][c] = 0.f;

        #pragma unroll
        for (int kk = 0; kk < 4; ++kk) {
            uint32_t kof = (uint32_t)(kk * 16 * 2);
            uint32_t aqh[2][4], aql[2][4], bkh[4][2], bkl[4][2];
            #pragma unroll
            for (int mi = 0; mi < 2; ++mi) {
                uint32_t mo = (uint32_t)((wm * 32 + mi * 16) * APAD * 2) + kof;
                LDSM4(aqh[mi], smb + SQH + mo + offA);
                LDSM4(aql[mi], smb + SQL + mo + offA);
            }
            #pragma unroll
            for (int nf2 = 0; nf2 < 2; ++nf2) {
                uint32_t no = (uint32_t)((wn * 32 + nf2 * 16) * APAD * 2) + kof;
                uint32_t t4[4];
                LDSM4(t4, smb + SKH + no + offB);
                bkh[2*nf2][0] = t4[0]; bkh[2*nf2][1] = t4[1];
                bkh[2*nf2+1][0] = t4[2]; bkh[2*nf2+1][1] = t4[3];
                LDSM4(t4, smb + SKL + no + offB);
                bkl[2*nf2][0] = t4[0]; bkl[2*nf2][1] = t4[1];
                bkl[2*nf2+1][0] = t4[2]; bkl[2*nf2+1][1] = t4[3];
            }
            #pragma unroll
            for (int mi = 0; mi < 2; ++mi)
                #pragma unroll
                for (int ni = 0; ni < 4; ++ni) {
                    MMA_BF16(sacc[mi][ni], aqh[mi], bkh[ni]);
                    MMA_BF16(sacc[mi][ni], aqh[mi], bkl[ni]);
                    MMA_BF16(sacc[mi][ni], aql[mi], bkh[ni]);
                }
        }

        // ---- mask + exp + split P, repack C-frag -> A-frag (no shuffles)
        uint32_t aPh[2][2][4], aPl[2][2][4];
        #pragma unroll
        for (int mi = 0; mi < 2; ++mi) {
            int L = Lm[mi];
            #pragma unroll
            for (int ni = 0; ni < 4; ++ni) {
                int g0 = j0 + wn * 32 + ni * 8 + 2 * (lane & 3);
                bool a0 = (g0 < L), a1 = (g0 + 1 < L);
                float p0 = a0 ? __expf(sacc[mi][ni][0] * 0.125f) : 0.f;
                float p1 = a1 ? __expf(sacc[mi][ni][1] * 0.125f) : 0.f;
                float p2 = a0 ? __expf(sacc[mi][ni][2] * 0.125f) : 0.f;
                float p3 = a1 ? __expf(sacc[mi][ni][3] * 0.125f) : 0.f;
                dsum[mi][0] += p0 + p1;
                dsum[mi][1] += p2 + p3;
                __nv_bfloat16 h0 = __float2bfloat16_rn(p0);
                __nv_bfloat16 h1 = __float2bfloat16_rn(p1);
                __nv_bfloat16 h2 = __float2bfloat16_rn(p2);
                __nv_bfloat16 h3 = __float2bfloat16_rn(p3);
                float q0 = p0 - __bfloat162float(h0);
                float q1 = p1 - __bfloat162float(h1);
                float q2 = p2 - __bfloat162float(h2);
                float q3 = p3 - __bfloat162float(h3);
                int kp = ni >> 1, hf = ni & 1;
                aPh[mi][kp][2*hf + 0] = pack_bf162(h0, h1);
                aPh[mi][kp][2*hf + 1] = pack_bf162(h2, h3);
                aPl[mi][kp][2*hf + 0] = pack_bf162(__float2bfloat16_rn(q0),
                                                   __float2bfloat16_rn(q1));
                aPl[mi][kp][2*hf + 1] = pack_bf162(__float2bfloat16_rn(q2),
                                                   __float2bfloat16_rn(q3));
            }
        }

        // ---- ctx += P @ V  (3-pass split), warp keys slice = wn*32 .. +31
        #pragma unroll
        for (int kk2 = 0; kk2 < 2; ++kk2) {
            uint32_t bvh[8][2], bvl[8][2];
            #pragma unroll
            for (int nf2 = 0; nf2 < 4; ++nf2) {
                uint32_t no = (uint32_t)((nf2 * 16) * APAD * 2
                                        + (wn * 32 + kk2 * 16) * 2);
                uint32_t t4[4];
                LDSM4(t4, smb + SVH + no + offB);
                bvh[2*nf2][0] = t4[0]; bvh[2*nf2][1] = t4[1];
                bvh[2*nf2+1][0] = t4[2]; bvh[2*nf2+1][1] = t4[3];
                LDSM4(t4, smb + SVL + no + offB);
                bvl[2*nf2][0] = t4[0]; bvl[2*nf2][1] = t4[1];
                bvl[2*nf2+1][0] = t4[2]; bvl[2*nf2+1][1] = t4[3];
            }
            #pragma unroll
            for (int mi = 0; mi < 2; ++mi)
                #pragma unroll
                for (int nf = 0; nf < 8; ++nf) {
                    MMA_BF16(cacc[mi][nf], aPh[mi][kk2], bvh[nf]);
                    MMA_BF16(cacc[mi][nf], aPh[mi][kk2], bvl[nf]);
                    MMA_BF16(cacc[mi][nf], aPl[mi][kk2], bvh[nf]);
                }
        }
        __syncthreads();
    }

    // ---- quad-reduce denominators (rows spread over lane%4)
    #pragma unroll
    for (int mi = 0; mi < 2; ++mi)
        #pragma unroll
        for (int hf = 0; hf < 2; ++hf) {
            float v = dsum[mi][hf];
            v += __shfl_xor_sync(0xffffffffu, v, 1);
            v += __shfl_xor_sync(0xffffffffu, v, 2);
            dsum[mi][hf] = v;
        }

    // ---- cross-warp (wn) reduction via smem aliased over Q region
    float* ctxbuf = (float*)sm;                 // [128][66]
    float* dnb    = (float*)sm + 128 * 66;      // [128]

    if (wn == 0) {
        int r0 = wm * 32 + (lane >> 2);
        #pragma unroll
        for (int mi = 0; mi < 2; ++mi) {
            if ((lane & 3) == 0) {
                dnb[r0 + mi * 16]     = dsum[mi][0];
                dnb[r0 + mi * 16 + 8] = dsum[mi][1];
            }
            #pragma unroll
            for (int nf = 0; nf < 8; ++nf) {
                int col = nf * 8 + 2 * (lane & 3);
                *(float2*)&ctxbuf[(r0 + mi * 16) * 66 + col] =
                    make_float2(cacc[mi][nf][0], cacc[mi][nf][1]);
                *(float2*)&ctxbuf[(r0 + mi * 16 + 8) * 66 + col] =
                    make_float2(cacc[mi][nf][2], cacc[mi][nf][3]);
            }
        }
    }
    __syncthreads();

    if (wn == 1) {
        int bh = b * NH + h;
        int r0 = wm * 32 + (lane >> 2);
        #pragma unroll
        for (int mi = 0; mi < 2; ++mi) {
            int rA = r0 + mi * 16, rB = rA + 8;
            float zc = (float)(SS - Lm[mi]);
            float di0 = 1.f / (dsum[mi][0] + dnb[rA] + zc);
            float di1 = 1.f / (dsum[mi][1] + dnb[rB] + zc);
            int blkp1 = Lm[mi] >> 5;
            const float* suf = vsuf + ((size_t)bh * 65 + blkp1) * HD;
            #pragma unroll
            for (int nf = 0; nf < 8; ++nf) {
                int col = nf * 8 + 2 * (lane & 3);
                float2 o0 = *(float2*)&ctxbuf[rA * 66 + col];
                float2 o1 = *(float2*)&ctxbuf[rB * 66 + col];
                float2 sv = *(const float2*)(suf + col);
                float2 w0 = make_float2((cacc[mi][nf][0] + o0.x + sv.x) * di0,
                                        (cacc[mi][nf][1] + o0.y + sv.y) * di0);
                float2 w1 = make_float2((cacc[mi][nf][2] + o1.x + sv.x) * di1,
                                        (cacc[mi][nf][3] + o1.y + sv.y) * di1);
                *(float2*)(gctx + base + (size_t)(m0 + rA) * HH + col) = w0;
                *(float2*)(gctx + base + (size_t)(m0 + rB) * HH + col) = w1;
            }
        }
    }
}

// ---------------------------------------------------------------------------
extern "C" void kernel_launch(void* const* d_in, const int* in_sizes, int n_in,
                              void* d_out, int out_size)
{
    const float* x  = (const float*)d_in[0];
    const float* Wq = (const float*)d_in[1];
    const float* bq = (const float*)d_in[2];
    const float* Wk = (const float*)d_in[3];
    const float* bk = (const float*)d_in[4];
    const float* Wv = (const float*)d_in[5];
    const float* bv = (const float*)d_in[6];
    const float* Wo = (const float*)d_in[7];
    const float* bo = (const float*)d_in[8];
    float* out = (float*)d_out;

    float *q, *k, *v, *ctx, *vsuf;
    cudaGetSymbolAddress((void**)&q,    g_q);
    cudaGetSymbolAddress((void**)&k,    g_k);
    cudaGetSymbolAddress((void**)&v,    g_v);
    cudaGetSymbolAddress((void**)&ctx,  g_ctx);
    cudaGetSymbolAddress((void**)&vsuf, g_vsuf);

    cudaFuncSetAttribute(gemm_tc, cudaFuncAttributeMaxDynamicSharedMemorySize,
                         GEMM_SMEM);
    cudaFuncSetAttribute(attn_mma, cudaFuncAttributeMaxDynamicSharedMemorySize,
                         ATTN_SMEM);

    // 1) fused QKV projections (mma.sync tensor cores, bf16 split)
    gemm_tc<<<dim3(8, 32, 3), 512, GEMM_SMEM>>>(x, Wq, Wk, Wv, bq, bk, bv, q, k, v);

    // 2) suffix sums of V
    suffix_kernel<<<32, 256>>>(v, vsuf);

    // 3) block-causal attention with zero-score correction (tensor cores)
    attn_mma<<<dim3(16, NH, BB), 256, ATTN_SMEM>>>(q, k, v, vsuf, ctx);

    // 4) output projection -> d_out
    gemm_tc<<<dim3(8, 32, 1), 512, GEMM_SMEM>>>(ctx, Wo, Wo, Wo, bo, bo, bo, out, out, out);
}

// round 15
// speedup vs baseline: 1.6593x; 1.5348x over previous
#include <cuda_runtime.h>
#include <cuda_bf16.h>
#include <cuda_fp16.h>
#include <cstdint>
#include <stdint.h>
#include <math.h>

#define BB 2
#define SS 2048
#define HH 1024
#define NH 16
#define HD 64
#define MTOT (BB*SS)   // 4096

// Scratch (static device allocation — allowed)
__device__ float g_q[MTOT*HH];
__device__ float g_k[MTOT*HH];
__device__ float g_v[MTOT*HH];
__device__ float g_ctx[MTOT*HH];
__device__ float g_vsuf[BB*NH*65*HD];

// ===========================================================================
// Helpers (sm_80+ portable: ldmatrix + mma.sync, fp16)
// ===========================================================================
__device__ __forceinline__ uint32_t smem_to_u32(const void* smem_ptr) {
    uint32_t addr;
    asm("{ .reg .u64 tmp; cvta.to.shared.u64 tmp, %1; cvt.u32.u64 %0, tmp; }"
        : "=r"(addr) : "l"(smem_ptr));
    return addr;
}

#define LDSM4(r, addr) \
    asm volatile("ldmatrix.sync.aligned.m8n8.x4.shared.b16 {%0,%1,%2,%3}, [%4];" \
        : "=r"((r)[0]), "=r"((r)[1]), "=r"((r)[2]), "=r"((r)[3]) : "r"(addr))

#define MMA_F16(d, a, b) \
    asm volatile("mma.sync.aligned.m16n8k16.row.col.f32.f16.f16.f32 " \
        "{%0,%1,%2,%3}, {%4,%5,%6,%7}, {%8,%9}, {%0,%1,%2,%3};" \
        : "+f"((d)[0]), "+f"((d)[1]), "+f"((d)[2]), "+f"((d)[3]) \
        : "r"((a)[0]), "r"((a)[1]), "r"((a)[2]), "r"((a)[3]), \
          "r"((b)[0]), "r"((b)[1]))

#define STS64V(addr, r0, r1) \
    asm volatile("st.shared.v2.b32 [%0], {%1, %2};" :: "r"(addr), "r"(r0), "r"(r1) : "memory")

__device__ __forceinline__ uint32_t pack_h2(float x, float y) {
    __half2 t = __halves2half2(__float2half_rn(x), __float2half_rn(y));
    return *reinterpret_cast<uint32_t*>(&t);
}

// ===========================================================================
// Tensor-core GEMM via mma.sync fp16: C[m,n] = sum_k A[m,k]*W[n,k] + bias[n]
// M=4096, N=1024, K=1024. CTA 128x128, BK=32, 512 thr (16 warps @ 32x32).
// Single-pass fp16, fp32 accum.
// SMEM per stage: Ah/Bh each 128 x 40 (pad) x 2B = 10240B -> stage 20480B.
// Double buffered = 40960B dynamic smem.
// ===========================================================================
#define SA 40                    // padded row stride in fp16 elems (80B)
#define AH_OFF 0u
#define BH_OFF 10240u
#define STAGE_BYTES 20480u
#define GEMM_SMEM (2*20480)

__global__ void __launch_bounds__(512) gemm_tc(
    const float* __restrict__ A,
    const float* __restrict__ W0, const float* __restrict__ W1, const float* __restrict__ W2,
    const float* __restrict__ bias0, const float* __restrict__ bias1, const float* __restrict__ bias2,
    float* __restrict__ C0, float* __restrict__ C1, float* __restrict__ C2)
{
    const float* W; const float* bias; float* C;
    if (blockIdx.z == 0)      { W = W0; bias = bias0; C = C0; }
    else if (blockIdx.z == 1) { W = W1; bias = bias1; C = C1; }
    else                      { W = W2; bias = bias2; C = C2; }

    extern __shared__ char sm_raw[];
    uint32_t smem_base = smem_to_u32(sm_raw);
    int tid  = threadIdx.x;
    int wid  = tid >> 5;
    int lane = tid & 31;
    int wm = wid >> 2;           // 0..3 (32 rows each)
    int wn = wid & 3;            // 0..3 (32 cols each)

    int m0 = blockIdx.y * 128;
    int n0 = blockIdx.x * 128;

    // gmem load mapping: thread t -> row t>>2, col (t&3)*8, 2 float4 per matrix
    int row = tid >> 2;
    int cb  = (tid & 3) * 8;
    const float* Ap = A + (size_t)(m0 + row) * HH + cb;
    const float* Wp = W + (size_t)(n0 + row) * HH + cb;
    uint32_t stsOff[2];
    #pragma unroll
    for (int f = 0; f < 2; ++f)
        stsOff[f] = (uint32_t)((row * SA + cb + 4 * f) * 2);

    uint32_t offA = (uint32_t)(((lane & 15) * SA + (lane >> 4) * 8) * 2);
    uint32_t offB = (uint32_t)((((lane & 7) + ((lane >> 4) << 3)) * SA
                               + ((lane >> 3) & 1) * 8) * 2);

    float acc[2][4][4];
    #pragma unroll
    for (int i = 0; i < 2; ++i)
        #pragma unroll
        for (int j = 0; j < 4; ++j)
            #pragma unroll
            for (int c = 0; c < 4; ++c) acc[i][j][c] = 0.f;

    // preload stage 0
    {
        uint32_t stg = smem_base;
        #pragma unroll
        for (int f = 0; f < 2; ++f) {
            float4 av = *(const float4*)(Ap + 4 * f);
            STS64V(stg + AH_OFF + stsOff[f], pack_h2(av.x, av.y), pack_h2(av.z, av.w));
            float4 wv = *(const float4*)(Wp + 4 * f);
            STS64V(stg + BH_OFF + stsOff[f], pack_h2(wv.x, wv.y), pack_h2(wv.z, wv.w));
        }
    }
    __syncthreads();

    const int NSTAGE = HH / 32;   // 32
    float4 pa[2], pw[2];

    for (int s = 0; s < NSTAGE; ++s) {
        if (s + 1 < NSTAGE) {
            int kt = (s + 1) * 32;
            #pragma unroll
            for (int f = 0; f < 2; ++f) {
                pa[f] = *(const float4*)(Ap + kt + 4 * f);
                pw[f] = *(const float4*)(Wp + kt + 4 * f);
            }
        }

        uint32_t stg = smem_base + (uint32_t)(s & 1) * STAGE_BYTES;
        uint32_t aBaseH = stg + AH_OFF + offA + (uint32_t)((wm * 32) * SA * 2);
        uint32_t bBaseH = stg + BH_OFF + offB + (uint32_t)((wn * 32) * SA * 2);

        #pragma unroll
        for (int ks = 0; ks < 2; ++ks) {
            uint32_t kOff = (uint32_t)(ks * 16 * 2);
            uint32_t ah[2][4], bh[4][2];
            #pragma unroll
            for (int mf = 0; mf < 2; ++mf) {
                uint32_t moff = (uint32_t)(mf * 16 * SA * 2) + kOff;
                LDSM4(ah[mf], aBaseH + moff);
            }
            #pragma unroll
            for (int nf2 = 0; nf2 < 2; ++nf2) {
                uint32_t noff = (uint32_t)(nf2 * 16 * SA * 2) + kOff;
                uint32_t t4[4];
                LDSM4(t4, bBaseH + noff);
                bh[2*nf2][0] = t4[0]; bh[2*nf2][1] = t4[1];
                bh[2*nf2+1][0] = t4[2]; bh[2*nf2+1][1] = t4[3];
            }
            #pragma unroll
            for (int mf = 0; mf < 2; ++mf)
                #pragma unroll
                for (int nf = 0; nf < 4; ++nf)
                    MMA_F16(acc[mf][nf], ah[mf], bh[nf]);
        }

        if (s + 1 < NSTAGE) {
            uint32_t nstg = smem_base + (uint32_t)((s + 1) & 1) * STAGE_BYTES;
            #pragma unroll
            for (int f = 0; f < 2; ++f) {
                STS64V(nstg + AH_OFF + stsOff[f], pack_h2(pa[f].x, pa[f].y),
                       pack_h2(pa[f].z, pa[f].w));
                STS64V(nstg + BH_OFF + stsOff[f], pack_h2(pw[f].x, pw[f].y),
                       pack_h2(pw[f].z, pw[f].w));
            }
        }
        __syncthreads();
    }

    // epilogue: acc -> C (+bias)
    int lq = lane >> 2;
    int lr = lane & 3;
    #pragma unroll
    for (int nf = 0; nf < 4; ++nf) {
        int gn = n0 + wn * 32 + nf * 8 + lr * 2;
        float b0 = bias[gn], b1 = bias[gn + 1];
        #pragma unroll
        for (int mf = 0; mf < 2; ++mf) {
            int gm = m0 + wm * 32 + mf * 16 + lq;
            *(float2*)(C + (size_t)gm * HH + gn) =
                make_float2(acc[mf][nf][0] + b0, acc[mf][nf][1] + b1);
            *(float2*)(C + (size_t)(gm + 8) * HH + gn) =
                make_float2(acc[mf][nf][2] + b0, acc[mf][nf][3] + b1);
        }
    }
}

// ---------------------------------------------------------------------------
// Suffix sums of V per (b,h): vsuf[bh][blk][d] = sum_{j >= blk*32} v[b,j,h,d]
// ---------------------------------------------------------------------------
__global__ void __launch_bounds__(256) suffix_kernel(const float* __restrict__ v,
                                                     float* __restrict__ vsuf)
{
    int bh = blockIdx.x;
    int b = bh >> 4, h = bh & 15;
    int d = threadIdx.x & 63;
    int g = threadIdx.x >> 6;

    __shared__ float ps[4][16][64];

    size_t vbase = (size_t)b * SS * HH + (size_t)h * HD + d;

    float acc = 0.f;
    for (int t = 15; t >= 0; --t) {
        int jbase = g * 512 + t * 32;
        #pragma unroll
        for (int jj = 31; jj >= 0; --jj)
            acc += v[vbase + (size_t)(jbase + jj) * HH];
        ps[g][t][d] = acc;
    }
    __syncthreads();

    float offset = 0.f;
    for (int g2 = g + 1; g2 < 4; ++g2) offset += ps[g2][0][d];

    for (int t = 0; t < 16; ++t) {
        int blk = g * 16 + t;
        vsuf[((size_t)bh * 65 + blk) * HD + d] = ps[g][t][d] + offset;
    }
    if (g == 3)
        vsuf[((size_t)bh * 65 + 64) * HD + d] = 0.f;
}

// ===========================================================================
// Tensor-core block-causal attention (single-pass fp16 mma.sync).
// CTA: 128 q-rows x 1 head. 8 warps: wm=wid>>1 (32 rows), wn=wid&1 (32 keys).
// SMEM fp16 (pad 72): Qh [128][72], Kh [64][72], Vth [64 d][72 keys].
// Tail reduction aliases fp32 ctxbuf[128][66] + dn[128] over the Q region.
// ===========================================================================
#define APAD 72
#define SQH 0
#define SKH 18432
#define SVH 27648
#define ATTN_SMEM 36864

__global__ void __launch_bounds__(256) attn_mma(
    const float* __restrict__ gq, const float* __restrict__ gk,
    const float* __restrict__ gv, const float* __restrict__ vsuf,
    float* __restrict__ gctx)
{
    int qt = (int)gridDim.x - 1 - (int)blockIdx.x;  // heavy tiles first
    int h  = blockIdx.y;
    int b  = blockIdx.z;

    extern __shared__ char sm[];
    uint32_t smb = smem_to_u32(sm);

    int tid = threadIdx.x;
    int wid = tid >> 5, lane = tid & 31;
    int wm = wid >> 1;            // 0..3 : rows wm*32
    int wn = wid & 1;             // 0..1 : keys wn*32
    int m0 = qt * 128;
    size_t base = (size_t)b * SS * HH + (size_t)h * HD;

    uint32_t offA = (uint32_t)(((lane & 15) * APAD + (lane >> 4) * 8) * 2);
    uint32_t offB = (uint32_t)((((lane & 7) + ((lane >> 4) << 3)) * APAD
                               + ((lane >> 3) & 1) * 8) * 2);

    // ---- load Q tile (fp16)
    {
        int row = tid >> 1, hc = (tid & 1) * 32;
        const float* Qp = gq + base + (size_t)(m0 + row) * HH + hc;
        #pragma unroll
        for (int f = 0; f < 8; ++f) {
            float4 qv = *(const float4*)(Qp + 4 * f);
            uint32_t o = (uint32_t)((row * APAD + hc + 4 * f) * 2);
            STS64V(smb + SQH + o, pack_h2(qv.x, qv.y), pack_h2(qv.z, qv.w));
        }
    }

    float cacc[2][8][4];
    #pragma unroll
    for (int mi = 0; mi < 2; ++mi)
        #pragma unroll
        for (int nf = 0; nf < 8; ++nf)
            #pragma unroll
            for (int c = 0; c < 4; ++c) cacc[mi][nf][c] = 0.f;
    float dsum[2][2] = {{0.f, 0.f}, {0.f, 0.f}};

    int Lm[2];
    #pragma unroll
    for (int mi = 0; mi < 2; ++mi)
        Lm[mi] = (((m0 + wm * 32 + mi * 16) >> 5) + 1) << 5;

    int nkt = 2 * qt + 2;
    for (int kt = 0; kt < nkt; ++kt) {
        int j0 = kt * 64;

        // ---- K tile [key][d] (fp16)
        {
            int row = tid >> 2, qc = (tid & 3) * 16;
            const float* Kp = gk + base + (size_t)(j0 + row) * HH + qc;
            #pragma unroll
            for (int f = 0; f < 4; ++f) {
                float4 kv = *(const float4*)(Kp + 4 * f);
                uint32_t o = (uint32_t)((row * APAD + qc + 4 * f) * 2);
                STS64V(smb + SKH + o, pack_h2(kv.x, kv.y), pack_h2(kv.z, kv.w));
            }
        }
        // ---- V tile transposed [d][key] (fp16, coalesced LDG: lane = d)
        {
            int d = tid & 63, jg = tid >> 6;
            const float* Vp = gv + base + d + (size_t)(j0 + jg * 16) * HH;
            __half* vh = (__half*)(sm + SVH);
            #pragma unroll
            for (int jj = 0; jj < 16; ++jj) {
                float val = Vp[(size_t)jj * HH];
                vh[d * APAD + jg * 16 + jj] = __float2half_rn(val);
            }
        }
        __syncthreads();

        // ---- S = Q @ K^T, warp tile 32 rows x 32 keys
        float sacc[2][4][4];
        #pragma unroll
        for (int mi = 0; mi < 2; ++mi)
            #pragma unroll
            for (int ni = 0; ni < 4; ++ni)
                #pragma unroll
                for (int c = 0; c < 4; ++c) sacc[mi][ni][c] = 0.f;

        #pragma unroll
        for (int kk = 0; kk < 4; ++kk) {
            uint32_t kof = (uint32_t)(kk * 16 * 2);
            uint32_t aqh[2][4], bkh[4][2];
            #pragma unroll
            for (int mi = 0; mi < 2; ++mi) {
                uint32_t mo = (uint32_t)((wm * 32 + mi * 16) * APAD * 2) + kof;
                LDSM4(aqh[mi], smb + SQH + mo + offA);
            }
            #pragma unroll
            for (int nf2 = 0; nf2 < 2; ++nf2) {
                uint32_t no = (uint32_t)((wn * 32 + nf2 * 16) * APAD * 2) + kof;
                uint32_t t4[4];
                LDSM4(t4, smb + SKH + no + offB);
                bkh[2*nf2][0] = t4[0]; bkh[2*nf2][1] = t4[1];
                bkh[2*nf2+1][0] = t4[2]; bkh[2*nf2+1][1] = t4[3];
            }
            #pragma unroll
            for (int mi = 0; mi < 2; ++mi)
                #pragma unroll
                for (int ni = 0; ni < 4; ++ni)
                    MMA_F16(sacc[mi][ni], aqh[mi], bkh[ni]);
        }

        // ---- mask + exp, repack P C-frag -> A-frag (fp16, no shuffles)
        uint32_t aPh[2][2][4];
        #pragma unroll
        for (int mi = 0; mi < 2; ++mi) {
            int L = Lm[mi];
            #pragma unroll
            for (int ni = 0; ni < 4; ++ni) {
                int g0 = j0 + wn * 32 + ni * 8 + 2 * (lane & 3);
                bool a0 = (g0 < L), a1 = (g0 + 1 < L);
                float p0 = a0 ? __expf(sacc[mi][ni][0] * 0.125f) : 0.f;
                float p1 = a1 ? __expf(sacc[mi][ni][1] * 0.125f) : 0.f;
                float p2 = a0 ? __expf(sacc[mi][ni][2] * 0.125f) : 0.f;
                float p3 = a1 ? __expf(sacc[mi][ni][3] * 0.125f) : 0.f;
                dsum[mi][0] += p0 + p1;
                dsum[mi][1] += p2 + p3;
                int kp = ni >> 1, hf = ni & 1;
                aPh[mi][kp][2*hf + 0] = pack_h2(p0, p1);
                aPh[mi][kp][2*hf + 1] = pack_h2(p2, p3);
            }
        }

        // ---- ctx += P @ V, warp keys slice = wn*32 .. +31
        #pragma unroll
        for (int kk2 = 0; kk2 < 2; ++kk2) {
            uint32_t bvh[8][2];
            #pragma unroll
            for (int nf2 = 0; nf2 < 4; ++nf2) {
                uint32_t no = (uint32_t)((nf2 * 16) * APAD * 2
                                        + (wn * 32 + kk2 * 16) * 2);
                uint32_t t4[4];
                LDSM4(t4, smb + SVH + no + offB);
                bvh[2*nf2][0] = t4[0]; bvh[2*nf2][1] = t4[1];
                bvh[2*nf2+1][0] = t4[2]; bvh[2*nf2+1][1] = t4[3];
            }
            #pragma unroll
            for (int mi = 0; mi < 2; ++mi)
                #pragma unroll
                for (int nf = 0; nf < 8; ++nf)
                    MMA_F16(cacc[mi][nf], aPh[mi][kk2], bvh[nf]);
        }
        __syncthreads();
    }

    // ---- quad-reduce denominators (rows spread over lane%4)
    #pragma unroll
    for (int mi = 0; mi < 2; ++mi)
        #pragma unroll
        for (int hf = 0; hf < 2; ++hf) {
            float v = dsum[mi][hf];
            v += __shfl_xor_sync(0xffffffffu, v, 1);
            v += __shfl_xor_sync(0xffffffffu, v, 2);
            dsum[mi][hf] = v;
        }

    // ---- cross-warp (wn) reduction via smem aliased over Q region
    float* ctxbuf = (float*)sm;                 // [128][66]
    float* dnb    = (float*)sm + 128 * 66;      // [128]

    if (wn == 0) {
        int r0 = wm * 32 + (lane >> 2);
        #pragma unroll
        for (int mi = 0; mi < 2; ++mi) {
            if ((lane & 3) == 0) {
                dnb[r0 + mi * 16]     = dsum[mi][0];
                dnb[r0 + mi * 16 + 8] = dsum[mi][1];
            }
            #pragma unroll
            for (int nf = 0; nf < 8; ++nf) {
                int col = nf * 8 + 2 * (lane & 3);
                *(float2*)&ctxbuf[(r0 + mi * 16) * 66 + col] =
                    make_float2(cacc[mi][nf][0], cacc[mi][nf][1]);
                *(float2*)&ctxbuf[(r0 + mi * 16 + 8) * 66 + col] =
                    make_float2(cacc[mi][nf][2], cacc[mi][nf][3]);
            }
        }
    }
    __syncthreads();

    if (wn == 1) {
        int bh = b * NH + h;
        int r0 = wm * 32 + (lane >> 2);
        #pragma unroll
        for (int mi = 0; mi < 2; ++mi) {
            int rA = r0 + mi * 16, rB = rA + 8;
            float zc = (float)(SS - Lm[mi]);
            float di0 = 1.f / (dsum[mi][0] + dnb[rA] + zc);
            float di1 = 1.f / (dsum[mi][1] + dnb[rB] + zc);
            int blkp1 = Lm[mi] >> 5;
            const float* suf = vsuf + ((size_t)bh * 65 + blkp1) * HD;
            #pragma unroll
            for (int nf = 0; nf < 8; ++nf) {
                int col = nf * 8 + 2 * (lane & 3);
                float2 o0 = *(float2*)&ctxbuf[rA * 66 + col];
                float2 o1 = *(float2*)&ctxbuf[rB * 66 + col];
                float2 sv = *(const float2*)(suf + col);
                float2 w0 = make_float2((cacc[mi][nf][0] + o0.x + sv.x) * di0,
                                        (cacc[mi][nf][1] + o0.y + sv.y) * di0);
                float2 w1 = make_float2((cacc[mi][nf][2] + o1.x + sv.x) * di1,
                                        (cacc[mi][nf][3] + o1.y + sv.y) * di1);
                *(float2*)(gctx + base + (size_t)(m0 + rA) * HH + col) = w0;
                *(float2*)(gctx + base + (size_t)(m0 + rB) * HH + col) = w1;
            }
        }
    }
}

// ---------------------------------------------------------------------------
extern "C" void kernel_launch(void* const* d_in, const int* in_sizes, int n_in,
                              void* d_out, int out_size)
{
    const float* x  = (const float*)d_in[0];
    const float* Wq = (const float*)d_in[1];
    const float* bq = (const float*)d_in[2];
    const float* Wk = (const float*)d_in[3];
    const float* bk = (const float*)d_in[4];
    const float* Wv = (const float*)d_in[5];
    const float* bv = (const float*)d_in[6];
    const float* Wo = (const float*)d_in[7];
    const float* bo = (const float*)d_in[8];
    float* out = (float*)d_out;

    float *q, *k, *v, *ctx, *vsuf;
    cudaGetSymbolAddress((void**)&q,    g_q);
    cudaGetSymbolAddress((void**)&k,    g_k);
    cudaGetSymbolAddress((void**)&v,    g_v);
    cudaGetSymbolAddress((void**)&ctx,  g_ctx);
    cudaGetSymbolAddress((void**)&vsuf, g_vsuf);

    cudaFuncSetAttribute(gemm_tc, cudaFuncAttributeMaxDynamicSharedMemorySize,
                         GEMM_SMEM);
    cudaFuncSetAttribute(attn_mma, cudaFuncAttributeMaxDynamicSharedMemorySize,
                         ATTN_SMEM);

    // 1) fused QKV projections (mma.sync fp16, single pass)
    gemm_tc<<<dim3(8, 32, 3), 512, GEMM_SMEM>>>(x, Wq, Wk, Wv, bq, bk, bv, q, k, v);

    // 2) suffix sums of V
    suffix_kernel<<<32, 256>>>(v, vsuf);

    // 3) block-causal attention with zero-score correction (fp16 tensor cores)
    attn_mma<<<dim3(16, NH, BB), 256, ATTN_SMEM>>>(q, k, v, vsuf, ctx);

    // 4) output projection -> d_out
    gemm_tc<<<dim3(8, 32, 1), 512, GEMM_SMEM>>>(ctx, Wo, Wo, Wo, bo, bo, bo, out, out, out);
}